// round 9
// baseline (speedup 1.0000x reference)
#include <cuda_runtime.h>
#include <cuda_bf16.h>
#include <cstdint>
#include <cstddef>

#define N_ 4096
#define Q_ 16384
#define B_ 2
typedef __nv_bfloat16 bf16;

// ---------------- static scratch ----------------
__device__ float d_f1[(size_t)B_ * 64 * N_];
__device__ float d_f2[(size_t)B_ * 128 * N_];
__device__ float d_f3[(size_t)B_ * 256 * N_];
__device__ float d_g[B_ * 256];
__device__ float4 d_wqgc[B_ * 256];
__device__ float d_G[(size_t)B_ * N_ * 256];
__device__ float4 d_knn[(size_t)B_ * Q_ * 2];
__device__ bf16 d_fTh[(size_t)B_ * N_ * 448];
__device__ bf16 d_fTl[(size_t)B_ * N_ * 448];
__device__ bf16 d_h1h[(size_t)B_ * Q_ * 256];
__device__ bf16 d_h1l[(size_t)B_ * Q_ * 256];
__device__ bf16 d_h2h[(size_t)B_ * Q_ * 128];
__device__ bf16 d_h2l[(size_t)B_ * Q_ * 128];
__device__ bf16 d_w1h[256 * 448];
__device__ bf16 d_w1l[256 * 448];
__device__ bf16 d_w2h[128 * 256];
__device__ bf16 d_w2l[128 * 256];
__device__ bf16 d_w3h[64 * 128];
__device__ bf16 d_w3l[64 * 128];

// ---------------- helpers ----------------
__device__ __forceinline__ uint32_t smem_u32(const void* p) {
    uint32_t a;
    asm("{ .reg .u64 t; cvta.to.shared.u64 t, %1; cvt.u32.u64 %0, t; }" : "=r"(a) : "l"(p));
    return a;
}
__device__ __forceinline__ void cp16(uint32_t s, const void* g) {
    asm volatile("cp.async.cg.shared.global [%0], [%1], 16;" :: "r"(s), "l"(g));
}
#define CP_COMMIT() asm volatile("cp.async.commit_group;" ::: "memory")
template<int NN> __device__ __forceinline__ void cp_wait() {
    asm volatile("cp.async.wait_group %0;" :: "n"(NN) : "memory");
}
#define MMA_BF16(d, a0, a1, a2, a3, b0, b1) \
    asm volatile("mma.sync.aligned.m16n8k16.row.col.f32.bf16.bf16.f32 " \
        "{%0,%1,%2,%3}, {%4,%5,%6,%7}, {%8,%9}, {%0,%1,%2,%3};" \
        : "+f"((d)[0]), "+f"((d)[1]), "+f"((d)[2]), "+f"((d)[3]) \
        : "r"(a0), "r"(a1), "r"(a2), "r"(a3), "r"(b0), "r"(b1))
#define LDSM_X4(r0, r1, r2, r3, addr) \
    asm volatile("ldmatrix.sync.aligned.m8n8.x4.shared.b16 {%0,%1,%2,%3}, [%4];" \
        : "=r"(r0), "=r"(r1), "=r"(r2), "=r"(r3) : "r"(addr))
#define LDSM_X2(r0, r1, addr) \
    asm volatile("ldmatrix.sync.aligned.m8n8.x2.shared.b16 {%0,%1}, [%2];" \
        : "=r"(r0), "=r"(r1) : "r"(addr))

__device__ __forceinline__ unsigned pack2b(float v0, float v1, unsigned& lo) {
    bf16 h0 = __float2bfloat16(v0), h1 = __float2bfloat16(v1);
    bf16 l0 = __float2bfloat16(v0 - __bfloat162float(h0));
    bf16 l1 = __float2bfloat16(v1 - __bfloat162float(h1));
    lo = (unsigned)__bfloat16_as_ushort(l0) | ((unsigned)__bfloat16_as_ushort(l1) << 16);
    return (unsigned)__bfloat16_as_ushort(h0) | ((unsigned)__bfloat16_as_ushort(h1) << 16);
}

// ---------------- feature extractor ----------------
__global__ void feat1_kernel(const float* __restrict__ orig,
                             const float* __restrict__ w1, const float* __restrict__ b1) {
    __shared__ float ws[192], bs[64];
    int tid = threadIdx.x;
    if (tid < 192) ws[tid] = w1[tid];
    if (tid < 64) bs[tid] = b1[tid];
    __syncthreads();
    int b = blockIdx.y, n = blockIdx.x * 256 + tid;
    const float* ob = orig + (size_t)b * 3 * N_;
    float x = ob[n], y = ob[N_ + n], z = ob[2 * N_ + n];
    #pragma unroll
    for (int c = 0; c < 64; c++) {
        float v = fmaf(ws[c * 3], x, fmaf(ws[c * 3 + 1], y, fmaf(ws[c * 3 + 2], z, bs[c])));
        d_f1[((size_t)b * 64 + c) * N_ + n] = fmaxf(v, 0.f);
    }
}

template<int KIN>
__global__ void feat_layer_kernel(const float* __restrict__ fin, const float* __restrict__ wgt,
                                  const float* __restrict__ bias, float* __restrict__ fout, int MOUT) {
    __shared__ __align__(16) float ws[KIN][8];
    int b = blockIdx.z, c0 = blockIdx.y * 8, tid = threadIdx.x;
    for (int idx = tid; idx < KIN * 8; idx += 256)
        ws[idx / 8][idx % 8] = wgt[(size_t)(c0 + idx % 8) * KIN + idx / 8];
    __syncthreads();
    int n = blockIdx.x * 256 + tid;
    const float* fb = fin + (size_t)b * KIN * N_ + n;
    float acc[8] = {0, 0, 0, 0, 0, 0, 0, 0};
    #pragma unroll 4
    for (int k = 0; k < KIN; k++) {
        float v = fb[(size_t)k * N_];
        float4 w0 = *reinterpret_cast<const float4*>(&ws[k][0]);
        float4 w1v = *reinterpret_cast<const float4*>(&ws[k][4]);
        acc[0] = fmaf(w0.x, v, acc[0]); acc[1] = fmaf(w0.y, v, acc[1]);
        acc[2] = fmaf(w0.z, v, acc[2]); acc[3] = fmaf(w0.w, v, acc[3]);
        acc[4] = fmaf(w1v.x, v, acc[4]); acc[5] = fmaf(w1v.y, v, acc[5]);
        acc[6] = fmaf(w1v.z, v, acc[6]); acc[7] = fmaf(w1v.w, v, acc[7]);
    }
    #pragma unroll
    for (int cc = 0; cc < 8; cc++)
        fout[((size_t)b * MOUT + c0 + cc) * N_ + n] = fmaxf(acc[cc] + bias[c0 + cc], 0.f);
}

__global__ void gmax_kernel() {
    __shared__ float s[256];
    int b = blockIdx.y, c = blockIdx.x;
    const float4* p = reinterpret_cast<const float4*>(d_f3 + ((size_t)b * 256 + c) * N_);
    float m = -1e30f;
    for (int i = threadIdx.x; i < N_ / 4; i += 256) {
        float4 v = p[i];
        m = fmaxf(m, fmaxf(fmaxf(v.x, v.y), fmaxf(v.z, v.w)));
    }
    s[threadIdx.x] = m;
    __syncthreads();
    for (int st = 128; st > 0; st >>= 1) {
        if (threadIdx.x < st) s[threadIdx.x] = fmaxf(s[threadIdx.x], s[threadIdx.x + st]);
        __syncthreads();
    }
    if (threadIdx.x == 0) d_g[b * 256 + c] = s[0];
}

__global__ void gconst_kernel(const float* __restrict__ r1, const float* __restrict__ rb1) {
    __shared__ float gs[256];
    int b = blockIdx.x, m = threadIdx.x;
    gs[m] = d_g[b * 256 + m];
    __syncthreads();
    float a = rb1[m];
    const float* wr = r1 + (size_t)m * 707 + 451;
    #pragma unroll 4
    for (int c = 0; c < 256; c++) a = fmaf(wr[c], gs[c], a);
    d_wqgc[b * 256 + m] = make_float4(r1[(size_t)m * 707 + 0], r1[(size_t)m * 707 + 1],
                                      r1[(size_t)m * 707 + 2], a);
}

__global__ void build_fT_kernel() {
    __shared__ float t[32][33];
    int b = blockIdx.z, c0 = blockIdx.y * 32, n0 = blockIdx.x * 32;
    int tx = threadIdx.x, ty = threadIdx.y;
    #pragma unroll
    for (int r = 0; r < 32; r += 8) {
        int c = c0 + ty + r;
        const float* src;
        if (c < 64)       src = d_f1 + ((size_t)b * 64 + c) * N_;
        else if (c < 192) src = d_f2 + ((size_t)b * 128 + (c - 64)) * N_;
        else              src = d_f3 + ((size_t)b * 256 + (c - 192)) * N_;
        t[ty + r][tx] = src[n0 + tx];
    }
    __syncthreads();
    #pragma unroll
    for (int r = 0; r < 32; r += 8) {
        float v = t[tx][ty + r];
        bf16 h = __float2bfloat16(v);
        size_t o = ((size_t)b * N_ + n0 + ty + r) * 448 + c0 + tx;
        d_fTh[o] = h;
        d_fTl[o] = __float2bfloat16(v - __bfloat162float(h));
    }
}

__global__ void wprep_kernel(const float* __restrict__ src, int srcld, int Kdst, int coff,
                             bf16* __restrict__ dh, bf16* __restrict__ dl) {
    int m = blockIdx.x;
    for (int c = threadIdx.x; c < Kdst; c += blockDim.x) {
        float v = src[(size_t)m * srcld + coff + c];
        bf16 h = __float2bfloat16(v);
        dh[(size_t)m * Kdst + c] = h;
        dl[(size_t)m * Kdst + c] = __float2bfloat16(v - __bfloat162float(h));
    }
}

// ---------------- KNN(K=3), 8-way slice split + batch-of-4 min filter ----------------
// 32 queries/block, 8 threads/query, 512 pts/thread.
__global__ void knn_idx_kernel(const float* __restrict__ orig, const float* __restrict__ qpts) {
    extern __shared__ char smraw[];
    float4* op = reinterpret_cast<float4*>(smraw);                 // [4096]
    float* cd = reinterpret_cast<float*>(smraw + 65536);           // [32][8][3]
    int* ci = reinterpret_cast<int*>(smraw + 65536 + 3072);        // [32][8][3]
    int b = blockIdx.y;
    const float* ob = orig + (size_t)b * 3 * N_;
    for (int i = threadIdx.x; i < N_; i += 256) {
        float x = ob[i], y = ob[N_ + i], z = ob[2 * N_ + i];
        op[i] = make_float4(x, y, z, fmaf(x, x, fmaf(y, y, z * z)));
    }
    __syncthreads();

    const int ql = threadIdx.x & 31, sl = threadIdx.x >> 5;   // lanes = 32 queries, same slice
    const int q = blockIdx.x * 32 + ql;
    const float* qb = qpts + (size_t)b * 3 * Q_;
    const float qx = qb[q], qy = qb[Q_ + q], qz = qb[2 * Q_ + q];
    const float qa = -2.f * qx, qc = -2.f * qy, qd = -2.f * qz;

    float b0 = 1e30f, b1 = 1e30f, b2 = 1e30f;
    int i0 = -1, i1 = -1, i2 = -1;
    const int jbeg = sl * (N_ / 8);
    #pragma unroll 1
    for (int j = jbeg; j < jbeg + N_ / 8; j += 4) {
        float4 P0 = op[j], P1 = op[j + 1], P2 = op[j + 2], P3 = op[j + 3];
        float d0 = fmaf(P0.x, qa, fmaf(P0.y, qc, fmaf(P0.z, qd, P0.w)));
        float d1 = fmaf(P1.x, qa, fmaf(P1.y, qc, fmaf(P1.z, qd, P1.w)));
        float d2 = fmaf(P2.x, qa, fmaf(P2.y, qc, fmaf(P2.z, qd, P2.w)));
        float d3 = fmaf(P3.x, qa, fmaf(P3.y, qc, fmaf(P3.z, qd, P3.w)));
        float m = fminf(fminf(d0, d1), fminf(d2, d3));
        if (m < b2) {
            #pragma unroll
            for (int u = 0; u < 4; u++) {
                float d = (u == 0) ? d0 : (u == 1) ? d1 : (u == 2) ? d2 : d3;
                if (d < b2) {
                    int jj = j + u;
                    if (d < b1) {
                        b2 = b1; i2 = i1;
                        if (d < b0) { b1 = b0; i1 = i0; b0 = d; i0 = jj; }
                        else        { b1 = d; i1 = jj; }
                    } else { b2 = d; i2 = jj; }
                }
            }
        }
    }
    {
        int base = (ql * 8 + sl) * 3;
        cd[base + 0] = b0; cd[base + 1] = b1; cd[base + 2] = b2;
        ci[base + 0] = i0; ci[base + 1] = i1; ci[base + 2] = i2;
    }
    __syncthreads();

    if (threadIdx.x < 32) {
        const int qq = blockIdx.x * 32 + threadIdx.x;
        float m0 = 1e30f, m1 = 1e30f, m2 = 1e30f;
        int j0 = 0, j1 = 0, j2 = 0;
        int base = threadIdx.x * 24;
        #pragma unroll
        for (int c = 0; c < 24; c++) {
            float d = cd[base + c];
            int j = ci[base + c];
            if (d < m2) {
                if (d < m1) {
                    m2 = m1; j2 = j1;
                    if (d < m0) { m1 = m0; j1 = j0; m0 = d; j0 = j; }
                    else        { m1 = d; j1 = j; }
                } else { m2 = d; j2 = j; }
            }
        }
        const float tqx = qb[qq], tqy = qb[Q_ + qq], tqz = qb[2 * Q_ + qq];
        float4 P0 = op[j0], P1 = op[j1], P2 = op[j2];
        float dx, dy, dz;
        dx = tqx - P0.x; dy = tqy - P0.y; dz = tqz - P0.z;
        float e0 = sqrtf(fmaf(dx, dx, fmaf(dy, dy, dz * dz)));
        dx = tqx - P1.x; dy = tqy - P1.y; dz = tqz - P1.z;
        float e1 = sqrtf(fmaf(dx, dx, fmaf(dy, dy, dz * dz)));
        dx = tqx - P2.x; dy = tqy - P2.y; dz = tqz - P2.z;
        float e2 = sqrtf(fmaf(dx, dx, fmaf(dy, dy, dz * dz)));
        float r0 = 1.f / (e0 + 1e-8f);
        float r1 = 1.f / (e1 + 1e-8f);
        float r2 = 1.f / (e2 + 1e-8f);
        float s = r0 + r1 + r2;
        size_t o = ((size_t)b * Q_ + qq) * 2;
        d_knn[o] = make_float4(__int_as_float(j0), __int_as_float(j1), __int_as_float(j2), r0 / s);
        d_knn[o + 1] = make_float4(r1 / s, r2 / s, 0.f, 0.f);
    }
}

// ---------------- gather G rows + fused layer-1 ----------------
__global__ void gather_h1_kernel(const float* __restrict__ qpts) {
    __shared__ float4 swq[256];
    int b = blockIdx.y;
    for (int i = threadIdx.x; i < 256; i += blockDim.x) swq[i] = d_wqgc[b * 256 + i];
    __syncthreads();
    int q = blockIdx.x * blockDim.x + threadIdx.x;
    const float* qb = qpts + (size_t)b * 3 * Q_;
    float qx = qb[q], qy = qb[Q_ + q], qz = qb[2 * Q_ + q];
    size_t o = ((size_t)b * Q_ + q) * 2;
    float4 rec0 = d_knn[o], rec1 = d_knn[o + 1];
    int i0 = __float_as_int(rec0.x), i1 = __float_as_int(rec0.y), i2 = __float_as_int(rec0.z);
    float w0 = rec0.w, w1 = rec1.x, w2 = rec1.y;

    const float4* G0 = reinterpret_cast<const float4*>(d_G + ((size_t)b * N_ + i0) * 256);
    const float4* G1 = reinterpret_cast<const float4*>(d_G + ((size_t)b * N_ + i1) * 256);
    const float4* G2 = reinterpret_cast<const float4*>(d_G + ((size_t)b * N_ + i2) * 256);
    size_t ro = ((size_t)b * Q_ + q) * 256;
    uint2* rh = reinterpret_cast<uint2*>(d_h1h + ro);
    uint2* rl = reinterpret_cast<uint2*>(d_h1l + ro);
    #pragma unroll 4
    for (int c4 = 0; c4 < 64; c4++) {
        float4 g0 = G0[c4], g1 = G1[c4], g2 = G2[c4];
        float4 m0 = swq[c4 * 4 + 0], m1 = swq[c4 * 4 + 1];
        float4 m2 = swq[c4 * 4 + 2], m3 = swq[c4 * 4 + 3];
        float v0 = fmaf(w0, g0.x, fmaf(w1, g1.x, fmaf(w2, g2.x,
                   fmaf(qx, m0.x, fmaf(qy, m0.y, fmaf(qz, m0.z, m0.w))))));
        float v1 = fmaf(w0, g0.y, fmaf(w1, g1.y, fmaf(w2, g2.y,
                   fmaf(qx, m1.x, fmaf(qy, m1.y, fmaf(qz, m1.z, m1.w))))));
        float v2 = fmaf(w0, g0.z, fmaf(w1, g1.z, fmaf(w2, g2.z,
                   fmaf(qx, m2.x, fmaf(qy, m2.y, fmaf(qz, m2.z, m2.w))))));
        float v3 = fmaf(w0, g0.w, fmaf(w1, g1.w, fmaf(w2, g2.w,
                   fmaf(qx, m3.x, fmaf(qy, m3.y, fmaf(qz, m3.z, m3.w))))));
        v0 = fmaxf(v0, 0.f); v1 = fmaxf(v1, 0.f);
        v2 = fmaxf(v2, 0.f); v3 = fmaxf(v3, 0.f);
        uint2 hh, ll;
        hh.x = pack2b(v0, v1, ll.x);
        hh.y = pack2b(v2, v3, ll.y);
        rh[c4] = hh; rl[c4] = ll;
    }
}

// ---------------- split-bf16 GEMM via mma.sync + ldmatrix ----------------
// OUTMODE: 0 = f32 rows, 1 = bf16 hi/lo rows, 2 = fused final 64->1 dot
template<int BN, int NCHT, int KTOT, int NROWS, bool HASBIAS, bool RELU, int OUTMODE>
__global__ void __launch_bounds__(256)
wmma_layer(const bf16* __restrict__ Ah, const bf16* __restrict__ Al,
           const bf16* __restrict__ Bh, const bf16* __restrict__ Bl,
           const float* __restrict__ bias,
           const float* __restrict__ w4, const float* __restrict__ rb4,
           bf16* __restrict__ oh, bf16* __restrict__ ol, float* __restrict__ ofp) {
    constexpr int BKP = 40;
    constexpr int WN = BN / 32;
    constexpr int WM = 8 / WN;
    constexpr int TM = 128 / WM;
    constexpr int MT = TM / 16;
    constexpr int CH = KTOT / 32;
    constexpr int ABUF = 128 * BKP;
    constexpr int BBUF = BN * BKP;

    extern __shared__ char sm[];
    bf16* sA = reinterpret_cast<bf16*>(sm);
    bf16* sB = reinterpret_cast<bf16*>(sm) + 4 * ABUF;
    __shared__ float s_bias[BN];
    __shared__ float s_w4[OUTMODE == 2 ? 64 : 1];
    __shared__ float s_red[OUTMODE == 2 ? 128 : 1][OUTMODE == 2 ? 2 : 1];

    const int tid = threadIdx.x;
    const int lane = tid & 31, wid = tid >> 5;
    const int g = lane >> 2, t = lane & 3;
    const int wn = wid % WN, wm = wid / WN;
    const int mrow = wm * TM, nrow = wn * 32;
    const int b = blockIdx.z;
    const int q0 = blockIdx.x * 128;
    const int gy = blockIdx.y;
    const size_t bR = (size_t)b * NROWS;
    const int arow = (lane & 7) + ((lane >> 3) & 1) * 8;
    const int acol = (lane >> 4) * 8;
    const int l15 = lane & 15;
    const int brow = l15 & 7;
    const int bcol = ((l15 >> 3) & 1) * 8;

    if (HASBIAS)
        for (int i = tid; i < BN; i += 256) s_bias[i] = bias[gy * BN + i];
    if (OUTMODE == 2 && tid < 64) s_w4[tid] = w4[tid];

    float acc[MT][4][4];
    #pragma unroll
    for (int mt = 0; mt < MT; mt++)
        #pragma unroll
        for (int nt = 0; nt < 4; nt++)
            #pragma unroll
            for (int i = 0; i < 4; i++) acc[mt][nt][i] = 0.f;

    auto load_chunk = [&](int s, int buf) {
        const int k0 = s * 32;
        #pragma unroll
        for (int i = 0; i < 4; i++) {
            int idx = tid + i * 256;
            int sel = idx >> 9, w = idx & 511, row = w >> 2, c = w & 3;
            const bf16* src = (sel ? Al : Ah) + (bR + q0 + row) * (size_t)KTOT + k0 + c * 8;
            cp16(smem_u32(sA + (buf * 2 + sel) * ABUF + row * BKP + c * 8), src);
        }
        #pragma unroll
        for (int i = 0; i < (BN * 8) / 256; i++) {
            int idx = tid + i * 256;
            int sel = (idx >= BN * 4) ? 1 : 0;
            int w = idx - sel * BN * 4, row = w >> 2, c = w & 3;
            const bf16* src = (sel ? Bl : Bh) + (size_t)(gy * BN + row) * KTOT + k0 + c * 8;
            cp16(smem_u32(sB + (buf * 2 + sel) * BBUF + row * BKP + c * 8), src);
        }
        CP_COMMIT();
    };

    load_chunk(0, 0);
    #pragma unroll 1
    for (int s = 0; s < CH; s++) {
        const int buf = s & 1;
        if (s + 1 < CH) { load_chunk(s + 1, buf ^ 1); cp_wait<1>(); }
        else cp_wait<0>();
        __syncthreads();
        const bf16* A0 = sA + (buf * 2 + 0) * ABUF;
        const bf16* A1 = sA + (buf * 2 + 1) * ABUF;
        const bf16* B0 = sB + (buf * 2 + 0) * BBUF;
        const bf16* B1 = sB + (buf * 2 + 1) * BBUF;
        #pragma unroll
        for (int ks = 0; ks < 2; ks++) {
            const int kb0 = ks * 16;
            uint32_t bh[4][2], bl[4][2];
            #pragma unroll
            for (int nt = 0; nt < 4; nt++) {
                LDSM_X2(bh[nt][0], bh[nt][1],
                        smem_u32(B0 + (nrow + nt * 8 + brow) * BKP + kb0 + bcol));
                LDSM_X2(bl[nt][0], bl[nt][1],
                        smem_u32(B1 + (nrow + nt * 8 + brow) * BKP + kb0 + bcol));
            }
            #pragma unroll
            for (int mt = 0; mt < MT; mt++) {
                uint32_t ah0, ah1, ah2, ah3, al0, al1, al2, al3;
                LDSM_X4(ah0, ah1, ah2, ah3,
                        smem_u32(A0 + (mrow + mt * 16 + arow) * BKP + kb0 + acol));
                LDSM_X4(al0, al1, al2, al3,
                        smem_u32(A1 + (mrow + mt * 16 + arow) * BKP + kb0 + acol));
                #pragma unroll
                for (int nt = 0; nt < 4; nt++) {
                    MMA_BF16(acc[mt][nt], ah0, ah1, ah2, ah3, bh[nt][0], bh[nt][1]);
                    MMA_BF16(acc[mt][nt], ah0, ah1, ah2, ah3, bl[nt][0], bl[nt][1]);
                    MMA_BF16(acc[mt][nt], al0, al1, al2, al3, bh[nt][0], bh[nt][1]);
                }
            }
        }
        __syncthreads();
    }

    if (OUTMODE == 2) {
        float pr[MT][2];
        #pragma unroll
        for (int mt = 0; mt < MT; mt++) { pr[mt][0] = 0.f; pr[mt][1] = 0.f; }
        #pragma unroll
        for (int mt = 0; mt < MT; mt++) {
            #pragma unroll
            for (int nt = 0; nt < 4; nt++) {
                int nl = nrow + nt * 8 + t * 2;
                float bi0 = s_bias[nl], bi1 = s_bias[nl + 1];
                float w40 = s_w4[nl], w41 = s_w4[nl + 1];
                pr[mt][0] += fmaxf(acc[mt][nt][0] + bi0, 0.f) * w40
                           + fmaxf(acc[mt][nt][1] + bi1, 0.f) * w41;
                pr[mt][1] += fmaxf(acc[mt][nt][2] + bi0, 0.f) * w40
                           + fmaxf(acc[mt][nt][3] + bi1, 0.f) * w41;
            }
        }
        #pragma unroll
        for (int mt = 0; mt < MT; mt++) {
            #pragma unroll
            for (int j = 0; j < 2; j++) {
                float p = pr[mt][j];
                p += __shfl_down_sync(0xFFFFFFFFu, p, 1, 4);
                p += __shfl_down_sync(0xFFFFFFFFu, p, 2, 4);
                if (t == 0) s_red[mrow + mt * 16 + g + j * 8][wn] = p;
            }
        }
        __syncthreads();
        if (tid < 128)
            ofp[bR + q0 + tid] = s_red[tid][0] + s_red[tid][1] + rb4[0];
        return;
    }

    #pragma unroll
    for (int mt = 0; mt < MT; mt++) {
        #pragma unroll
        for (int nt = 0; nt < 4; nt++) {
            int nl = nrow + nt * 8 + t * 2;
            int nn = gy * BN + nl;
            float bi0 = HASBIAS ? s_bias[nl] : 0.f;
            float bi1 = HASBIAS ? s_bias[nl + 1] : 0.f;
            size_t r0 = bR + q0 + mrow + mt * 16 + g;
            size_t r1 = r0 + 8;
            float v00 = acc[mt][nt][0] + bi0, v01 = acc[mt][nt][1] + bi1;
            float v10 = acc[mt][nt][2] + bi0, v11 = acc[mt][nt][3] + bi1;
            if (RELU) {
                v00 = fmaxf(v00, 0.f); v01 = fmaxf(v01, 0.f);
                v10 = fmaxf(v10, 0.f); v11 = fmaxf(v11, 0.f);
            }
            if (OUTMODE == 1) {
                unsigned lo0, lo1;
                unsigned hi0 = pack2b(v00, v01, lo0);
                unsigned hi1 = pack2b(v10, v11, lo1);
                *reinterpret_cast<unsigned*>(oh + r0 * NCHT + nn) = hi0;
                *reinterpret_cast<unsigned*>(ol + r0 * NCHT + nn) = lo0;
                *reinterpret_cast<unsigned*>(oh + r1 * NCHT + nn) = hi1;
                *reinterpret_cast<unsigned*>(ol + r1 * NCHT + nn) = lo1;
            } else {
                *reinterpret_cast<float2*>(ofp + r0 * NCHT + nn) = make_float2(v00, v01);
                *reinterpret_cast<float2*>(ofp + r1 * NCHT + nn) = make_float2(v10, v11);
            }
        }
    }
}

// ---------------- launch ----------------
extern "C" void kernel_launch(void* const* d_in, const int* in_sizes, int n_in,
                              void* d_out, int out_size) {
    (void)in_sizes; (void)n_in; (void)out_size;
    const float* orig = (const float*)d_in[0];
    const float* qpts = (const float*)d_in[1];
    const float* w1 = (const float*)d_in[2];
    const float* b1 = (const float*)d_in[3];
    const float* w2 = (const float*)d_in[4];
    const float* b2 = (const float*)d_in[5];
    const float* w3 = (const float*)d_in[6];
    const float* b3 = (const float*)d_in[7];
    const float* r1 = (const float*)d_in[8];
    const float* rb1 = (const float*)d_in[9];
    const float* r2 = (const float*)d_in[10];
    const float* rb2 = (const float*)d_in[11];
    const float* r3 = (const float*)d_in[12];
    const float* rb3 = (const float*)d_in[13];
    const float* r4 = (const float*)d_in[14];
    const float* rb4 = (const float*)d_in[15];
    float* out = (float*)d_out;

    float *pf1, *pf2, *pf3, *pG;
    cudaGetSymbolAddress((void**)&pf1, d_f1);
    cudaGetSymbolAddress((void**)&pf2, d_f2);
    cudaGetSymbolAddress((void**)&pf3, d_f3);
    cudaGetSymbolAddress((void**)&pG, d_G);
    bf16 *pfTh, *pfTl, *pW1h, *pW1l, *pW2h, *pW2l, *pW3h, *pW3l;
    bf16 *pH1h, *pH1l, *pH2h, *pH2l;
    cudaGetSymbolAddress((void**)&pfTh, d_fTh);
    cudaGetSymbolAddress((void**)&pfTl, d_fTl);
    cudaGetSymbolAddress((void**)&pW1h, d_w1h);
    cudaGetSymbolAddress((void**)&pW1l, d_w1l);
    cudaGetSymbolAddress((void**)&pW2h, d_w2h);
    cudaGetSymbolAddress((void**)&pW2l, d_w2l);
    cudaGetSymbolAddress((void**)&pW3h, d_w3h);
    cudaGetSymbolAddress((void**)&pW3l, d_w3l);
    cudaGetSymbolAddress((void**)&pH1h, d_h1h);
    cudaGetSymbolAddress((void**)&pH1l, d_h1l);
    cudaGetSymbolAddress((void**)&pH2h, d_h2h);
    cudaGetSymbolAddress((void**)&pH2l, d_h2l);

    const int SM128 = (4 * 128 * 40 + 4 * 128 * 40) * 2;  // 81920
    const int SM64  = (4 * 128 * 40 + 4 * 64 * 40) * 2;   // 61440
    const int SMKNN = N_ * 16 + 32 * 8 * 3 * 8;           // 71680
    cudaFuncSetAttribute(wmma_layer<128, 256, 448, N_, false, false, 0>,
                         cudaFuncAttributeMaxDynamicSharedMemorySize, SM128);
    cudaFuncSetAttribute(wmma_layer<128, 128, 256, Q_, true, true, 1>,
                         cudaFuncAttributeMaxDynamicSharedMemorySize, SM128);
    cudaFuncSetAttribute(wmma_layer<64, 64, 128, Q_, true, true, 2>,
                         cudaFuncAttributeMaxDynamicSharedMemorySize, SM64);
    cudaFuncSetAttribute(knn_idx_kernel,
                         cudaFuncAttributeMaxDynamicSharedMemorySize, SMKNN);

    feat1_kernel<<<dim3(N_ / 256, B_), 256>>>(orig, w1, b1);
    feat_layer_kernel<64><<<dim3(N_ / 256, 16, B_), 256>>>(pf1, w2, b2, pf2, 128);
    feat_layer_kernel<128><<<dim3(N_ / 256, 32, B_), 256>>>(pf2, w3, b3, pf3, 256);
    knn_idx_kernel<<<dim3(Q_ / 32, B_), 256, SMKNN>>>(orig, qpts);   // profiled slot
    gmax_kernel<<<dim3(256, B_), 256>>>();
    gconst_kernel<<<B_, 256>>>(r1, rb1);
    build_fT_kernel<<<dim3(N_ / 32, 14, B_), dim3(32, 8)>>>();
    wprep_kernel<<<256, 128>>>(r1, 707, 448, 3, pW1h, pW1l);
    wprep_kernel<<<128, 128>>>(r2, 256, 256, 0, pW2h, pW2l);
    wprep_kernel<<<64, 128>>>(r3, 128, 128, 0, pW3h, pW3l);

    wmma_layer<128, 256, 448, N_, false, false, 0><<<dim3(N_ / 128, 2, B_), 256, SM128>>>(
        pfTh, pfTl, pW1h, pW1l, nullptr, nullptr, nullptr, nullptr, nullptr, pG);
    gather_h1_kernel<<<dim3(Q_ / 256, B_), 256>>>(qpts);
    wmma_layer<128, 128, 256, Q_, true, true, 1><<<dim3(Q_ / 128, 1, B_), 256, SM128>>>(
        pH1h, pH1l, pW2h, pW2l, rb2, nullptr, nullptr, pH2h, pH2l, nullptr);
    wmma_layer<64, 64, 128, Q_, true, true, 2><<<dim3(Q_ / 128, 1, B_), 256, SM64>>>(
        pH2h, pH2l, pW3h, pW3l, rb3, r4, rb4, nullptr, nullptr, out);
}

// round 13
// speedup vs baseline: 1.1653x; 1.1653x over previous
#include <cuda_runtime.h>
#include <cuda_bf16.h>
#include <cstdint>
#include <cstddef>

#define N_ 4096
#define Q_ 16384
#define B_ 2
typedef __nv_bfloat16 bf16;

// ---------------- static scratch ----------------
__device__ float d_f1[(size_t)B_ * 64 * N_];
__device__ float d_f2[(size_t)B_ * 128 * N_];
__device__ float d_f3[(size_t)B_ * 256 * N_];
__device__ float d_g[B_ * 256];
__device__ float4 d_wqgc[B_ * 256];
__device__ float d_G[(size_t)B_ * N_ * 256];
__device__ float4 d_knn[(size_t)B_ * Q_ * 2];
__device__ bf16 d_fTh[(size_t)B_ * N_ * 448];
__device__ bf16 d_fTl[(size_t)B_ * N_ * 448];
__device__ bf16 d_h1h[(size_t)B_ * Q_ * 256];
__device__ bf16 d_h1l[(size_t)B_ * Q_ * 256];
__device__ bf16 d_h2h[(size_t)B_ * Q_ * 128];
__device__ bf16 d_h2l[(size_t)B_ * Q_ * 128];
__device__ bf16 d_w1h[256 * 448];
__device__ bf16 d_w1l[256 * 448];
__device__ bf16 d_w2h[128 * 256];
__device__ bf16 d_w2l[128 * 256];
__device__ bf16 d_w3h[64 * 128];
__device__ bf16 d_w3l[64 * 128];

// ---------------- helpers ----------------
__device__ __forceinline__ uint32_t smem_u32(const void* p) {
    uint32_t a;
    asm("{ .reg .u64 t; cvta.to.shared.u64 t, %1; cvt.u32.u64 %0, t; }" : "=r"(a) : "l"(p));
    return a;
}
__device__ __forceinline__ void cp16(uint32_t s, const void* g) {
    asm volatile("cp.async.cg.shared.global [%0], [%1], 16;" :: "r"(s), "l"(g));
}
#define CP_COMMIT() asm volatile("cp.async.commit_group;" ::: "memory")
template<int NN> __device__ __forceinline__ void cp_wait() {
    asm volatile("cp.async.wait_group %0;" :: "n"(NN) : "memory");
}
#define MMA_BF16(d, a0, a1, a2, a3, b0, b1) \
    asm volatile("mma.sync.aligned.m16n8k16.row.col.f32.bf16.bf16.f32 " \
        "{%0,%1,%2,%3}, {%4,%5,%6,%7}, {%8,%9}, {%0,%1,%2,%3};" \
        : "+f"((d)[0]), "+f"((d)[1]), "+f"((d)[2]), "+f"((d)[3]) \
        : "r"(a0), "r"(a1), "r"(a2), "r"(a3), "r"(b0), "r"(b1))
#define LDSM_X4(r0, r1, r2, r3, addr) \
    asm volatile("ldmatrix.sync.aligned.m8n8.x4.shared.b16 {%0,%1,%2,%3}, [%4];" \
        : "=r"(r0), "=r"(r1), "=r"(r2), "=r"(r3) : "r"(addr))
#define LDSM_X2(r0, r1, addr) \
    asm volatile("ldmatrix.sync.aligned.m8n8.x2.shared.b16 {%0,%1}, [%2];" \
        : "=r"(r0), "=r"(r1) : "r"(addr))

__device__ __forceinline__ unsigned pack2b(float v0, float v1, unsigned& lo) {
    bf16 h0 = __float2bfloat16(v0), h1 = __float2bfloat16(v1);
    bf16 l0 = __float2bfloat16(v0 - __bfloat162float(h0));
    bf16 l1 = __float2bfloat16(v1 - __bfloat162float(h1));
    lo = (unsigned)__bfloat16_as_ushort(l0) | ((unsigned)__bfloat16_as_ushort(l1) << 16);
    return (unsigned)__bfloat16_as_ushort(h0) | ((unsigned)__bfloat16_as_ushort(h1) << 16);
}

// ---------------- feature extractor ----------------
__global__ void feat1_kernel(const float* __restrict__ orig,
                             const float* __restrict__ w1, const float* __restrict__ b1) {
    __shared__ float ws[192], bs[64];
    int tid = threadIdx.x;
    if (tid < 192) ws[tid] = w1[tid];
    if (tid < 64) bs[tid] = b1[tid];
    __syncthreads();
    int b = blockIdx.y, n = blockIdx.x * 256 + tid;
    const float* ob = orig + (size_t)b * 3 * N_;
    float x = ob[n], y = ob[N_ + n], z = ob[2 * N_ + n];
    #pragma unroll
    for (int c = 0; c < 64; c++) {
        float v = fmaf(ws[c * 3], x, fmaf(ws[c * 3 + 1], y, fmaf(ws[c * 3 + 2], z, bs[c])));
        d_f1[((size_t)b * 64 + c) * N_ + n] = fmaxf(v, 0.f);
    }
}

template<int KIN>
__global__ void feat_layer_kernel(const float* __restrict__ fin, const float* __restrict__ wgt,
                                  const float* __restrict__ bias, float* __restrict__ fout, int MOUT) {
    __shared__ __align__(16) float ws[KIN][8];
    int b = blockIdx.z, c0 = blockIdx.y * 8, tid = threadIdx.x;
    for (int idx = tid; idx < KIN * 8; idx += 256)
        ws[idx / 8][idx % 8] = wgt[(size_t)(c0 + idx % 8) * KIN + idx / 8];
    __syncthreads();
    int n = blockIdx.x * 256 + tid;
    const float* fb = fin + (size_t)b * KIN * N_ + n;
    float acc[8] = {0, 0, 0, 0, 0, 0, 0, 0};
    #pragma unroll 4
    for (int k = 0; k < KIN; k++) {
        float v = fb[(size_t)k * N_];
        float4 w0 = *reinterpret_cast<const float4*>(&ws[k][0]);
        float4 w1v = *reinterpret_cast<const float4*>(&ws[k][4]);
        acc[0] = fmaf(w0.x, v, acc[0]); acc[1] = fmaf(w0.y, v, acc[1]);
        acc[2] = fmaf(w0.z, v, acc[2]); acc[3] = fmaf(w0.w, v, acc[3]);
        acc[4] = fmaf(w1v.x, v, acc[4]); acc[5] = fmaf(w1v.y, v, acc[5]);
        acc[6] = fmaf(w1v.z, v, acc[6]); acc[7] = fmaf(w1v.w, v, acc[7]);
    }
    #pragma unroll
    for (int cc = 0; cc < 8; cc++)
        fout[((size_t)b * MOUT + c0 + cc) * N_ + n] = fmaxf(acc[cc] + bias[c0 + cc], 0.f);
}

__global__ void gmax_kernel() {
    __shared__ float s[256];
    int b = blockIdx.y, c = blockIdx.x;
    const float4* p = reinterpret_cast<const float4*>(d_f3 + ((size_t)b * 256 + c) * N_);
    float m = -1e30f;
    for (int i = threadIdx.x; i < N_ / 4; i += 256) {
        float4 v = p[i];
        m = fmaxf(m, fmaxf(fmaxf(v.x, v.y), fmaxf(v.z, v.w)));
    }
    s[threadIdx.x] = m;
    __syncthreads();
    for (int st = 128; st > 0; st >>= 1) {
        if (threadIdx.x < st) s[threadIdx.x] = fmaxf(s[threadIdx.x], s[threadIdx.x + st]);
        __syncthreads();
    }
    if (threadIdx.x == 0) d_g[b * 256 + c] = s[0];
}

__global__ void gconst_kernel(const float* __restrict__ r1, const float* __restrict__ rb1) {
    __shared__ float gs[256];
    int b = blockIdx.x, m = threadIdx.x;
    gs[m] = d_g[b * 256 + m];
    __syncthreads();
    float a = rb1[m];
    const float* wr = r1 + (size_t)m * 707 + 451;
    #pragma unroll 4
    for (int c = 0; c < 256; c++) a = fmaf(wr[c], gs[c], a);
    d_wqgc[b * 256 + m] = make_float4(r1[(size_t)m * 707 + 0], r1[(size_t)m * 707 + 1],
                                      r1[(size_t)m * 707 + 2], a);
}

__global__ void build_fT_kernel() {
    __shared__ float t[32][33];
    int b = blockIdx.z, c0 = blockIdx.y * 32, n0 = blockIdx.x * 32;
    int tx = threadIdx.x, ty = threadIdx.y;
    #pragma unroll
    for (int r = 0; r < 32; r += 8) {
        int c = c0 + ty + r;
        const float* src;
        if (c < 64)       src = d_f1 + ((size_t)b * 64 + c) * N_;
        else if (c < 192) src = d_f2 + ((size_t)b * 128 + (c - 64)) * N_;
        else              src = d_f3 + ((size_t)b * 256 + (c - 192)) * N_;
        t[ty + r][tx] = src[n0 + tx];
    }
    __syncthreads();
    #pragma unroll
    for (int r = 0; r < 32; r += 8) {
        float v = t[tx][ty + r];
        bf16 h = __float2bfloat16(v);
        size_t o = ((size_t)b * N_ + n0 + ty + r) * 448 + c0 + tx;
        d_fTh[o] = h;
        d_fTl[o] = __float2bfloat16(v - __bfloat162float(h));
    }
}

__global__ void wprep_kernel(const float* __restrict__ src, int srcld, int Kdst, int coff,
                             bf16* __restrict__ dh, bf16* __restrict__ dl) {
    int m = blockIdx.x;
    for (int c = threadIdx.x; c < Kdst; c += blockDim.x) {
        float v = src[(size_t)m * srcld + coff + c];
        bf16 h = __float2bfloat16(v);
        dh[(size_t)m * Kdst + c] = h;
        dl[(size_t)m * Kdst + c] = __float2bfloat16(v - __bfloat162float(h));
    }
}

// ---------------- KNN(K=3), 4-way slice split (exact, R8-proven) ----------------
__global__ void knn_idx_kernel(const float* __restrict__ orig, const float* __restrict__ qpts) {
    extern __shared__ char smraw[];
    float4* op = reinterpret_cast<float4*>(smraw);                 // [4096]
    float* cd = reinterpret_cast<float*>(smraw + 65536);           // [64][4][3]
    int* ci = reinterpret_cast<int*>(smraw + 65536 + 3072);        // [64][4][3]
    int b = blockIdx.y;
    const float* ob = orig + (size_t)b * 3 * N_;
    for (int i = threadIdx.x; i < N_; i += 256) {
        float x = ob[i], y = ob[N_ + i], z = ob[2 * N_ + i];
        op[i] = make_float4(x, y, z, fmaf(x, x, fmaf(y, y, z * z)));
    }
    __syncthreads();

    const int ql = threadIdx.x & 63, sl = threadIdx.x >> 6;
    const int q = blockIdx.x * 64 + ql;
    const float* qb = qpts + (size_t)b * 3 * Q_;
    const float qx = qb[q], qy = qb[Q_ + q], qz = qb[2 * Q_ + q];
    const float qa = -2.f * qx, qc = -2.f * qy, qd = -2.f * qz;

    float b0 = 1e30f, b1 = 1e30f, b2 = 1e30f;
    int i0 = -1, i1 = -1, i2 = -1;
    const int jbeg = sl * (N_ / 4), jend = jbeg + N_ / 4;
    #pragma unroll 4
    for (int j = jbeg; j < jend; j++) {
        float4 P = op[j];
        float d = fmaf(P.x, qa, fmaf(P.y, qc, fmaf(P.z, qd, P.w)));
        if (d < b2) {
            if (d < b1) {
                b2 = b1; i2 = i1;
                if (d < b0) { b1 = b0; i1 = i0; b0 = d; i0 = j; }
                else        { b1 = d; i1 = j; }
            } else { b2 = d; i2 = j; }
        }
    }
    {
        int base = (ql * 4 + sl) * 3;
        cd[base + 0] = b0; cd[base + 1] = b1; cd[base + 2] = b2;
        ci[base + 0] = i0; ci[base + 1] = i1; ci[base + 2] = i2;
    }
    __syncthreads();

    if (threadIdx.x < 64) {
        const int qq = blockIdx.x * 64 + threadIdx.x;
        float m0 = 1e30f, m1 = 1e30f, m2 = 1e30f;
        int j0 = 0, j1 = 0, j2 = 0;
        int base = threadIdx.x * 12;
        #pragma unroll
        for (int c = 0; c < 12; c++) {
            float d = cd[base + c];
            int j = ci[base + c];
            if (d < m2) {
                if (d < m1) {
                    m2 = m1; j2 = j1;
                    if (d < m0) { m1 = m0; j1 = j0; m0 = d; j0 = j; }
                    else        { m1 = d; j1 = j; }
                } else { m2 = d; j2 = j; }
            }
        }
        const float tqx = qb[qq], tqy = qb[Q_ + qq], tqz = qb[2 * Q_ + qq];
        float4 P0 = op[j0], P1 = op[j1], P2 = op[j2];
        float dx, dy, dz;
        dx = tqx - P0.x; dy = tqy - P0.y; dz = tqz - P0.z;
        float e0 = sqrtf(fmaf(dx, dx, fmaf(dy, dy, dz * dz)));
        dx = tqx - P1.x; dy = tqy - P1.y; dz = tqz - P1.z;
        float e1 = sqrtf(fmaf(dx, dx, fmaf(dy, dy, dz * dz)));
        dx = tqx - P2.x; dy = tqy - P2.y; dz = tqz - P2.z;
        float e2 = sqrtf(fmaf(dx, dx, fmaf(dy, dy, dz * dz)));
        float r0 = 1.f / (e0 + 1e-8f);
        float r1 = 1.f / (e1 + 1e-8f);
        float r2 = 1.f / (e2 + 1e-8f);
        float s = r0 + r1 + r2;
        size_t o = ((size_t)b * Q_ + qq) * 2;
        d_knn[o] = make_float4(__int_as_float(j0), __int_as_float(j1), __int_as_float(j2), r0 / s);
        d_knn[o + 1] = make_float4(r1 / s, r2 / s, 0.f, 0.f);
    }
}

// ---------------- gather G rows + fused layer-1 ----------------
__global__ void gather_h1_kernel(const float* __restrict__ qpts) {
    __shared__ float4 swq[256];
    int b = blockIdx.y;
    for (int i = threadIdx.x; i < 256; i += blockDim.x) swq[i] = d_wqgc[b * 256 + i];
    __syncthreads();
    int q = blockIdx.x * blockDim.x + threadIdx.x;
    const float* qb = qpts + (size_t)b * 3 * Q_;
    float qx = qb[q], qy = qb[Q_ + q], qz = qb[2 * Q_ + q];
    size_t o = ((size_t)b * Q_ + q) * 2;
    float4 rec0 = d_knn[o], rec1 = d_knn[o + 1];
    int i0 = __float_as_int(rec0.x), i1 = __float_as_int(rec0.y), i2 = __float_as_int(rec0.z);
    float w0 = rec0.w, w1 = rec1.x, w2 = rec1.y;

    const float4* G0 = reinterpret_cast<const float4*>(d_G + ((size_t)b * N_ + i0) * 256);
    const float4* G1 = reinterpret_cast<const float4*>(d_G + ((size_t)b * N_ + i1) * 256);
    const float4* G2 = reinterpret_cast<const float4*>(d_G + ((size_t)b * N_ + i2) * 256);
    size_t ro = ((size_t)b * Q_ + q) * 256;
    uint2* rh = reinterpret_cast<uint2*>(d_h1h + ro);
    uint2* rl = reinterpret_cast<uint2*>(d_h1l + ro);
    #pragma unroll 4
    for (int c4 = 0; c4 < 64; c4++) {
        float4 g0 = G0[c4], g1 = G1[c4], g2 = G2[c4];
        float4 m0 = swq[c4 * 4 + 0], m1 = swq[c4 * 4 + 1];
        float4 m2 = swq[c4 * 4 + 2], m3 = swq[c4 * 4 + 3];
        float v0 = fmaf(w0, g0.x, fmaf(w1, g1.x, fmaf(w2, g2.x,
                   fmaf(qx, m0.x, fmaf(qy, m0.y, fmaf(qz, m0.z, m0.w))))));
        float v1 = fmaf(w0, g0.y, fmaf(w1, g1.y, fmaf(w2, g2.y,
                   fmaf(qx, m1.x, fmaf(qy, m1.y, fmaf(qz, m1.z, m1.w))))));
        float v2 = fmaf(w0, g0.z, fmaf(w1, g1.z, fmaf(w2, g2.z,
                   fmaf(qx, m2.x, fmaf(qy, m2.y, fmaf(qz, m2.z, m2.w))))));
        float v3 = fmaf(w0, g0.w, fmaf(w1, g1.w, fmaf(w2, g2.w,
                   fmaf(qx, m3.x, fmaf(qy, m3.y, fmaf(qz, m3.z, m3.w))))));
        v0 = fmaxf(v0, 0.f); v1 = fmaxf(v1, 0.f);
        v2 = fmaxf(v2, 0.f); v3 = fmaxf(v3, 0.f);
        uint2 hh, ll;
        hh.x = pack2b(v0, v1, ll.x);
        hh.y = pack2b(v2, v3, ll.y);
        rh[c4] = hh; rl[c4] = ll;
    }
}

// ---------------- split-bf16 GEMM via mma.sync + ldmatrix ----------------
// OUTMODE: 0 = f32 rows, 1 = bf16 hi/lo rows, 2 = fused final 64->1 dot
template<int BN, int NCHT, int KTOT, int NROWS, bool HASBIAS, bool RELU, int OUTMODE>
__global__ void __launch_bounds__(256)
wmma_layer(const bf16* __restrict__ Ah, const bf16* __restrict__ Al,
           const bf16* __restrict__ Bh, const bf16* __restrict__ Bl,
           const float* __restrict__ bias,
           const float* __restrict__ w4, const float* __restrict__ rb4,
           bf16* __restrict__ oh, bf16* __restrict__ ol, float* __restrict__ ofp) {
    constexpr int BKP = 40;
    constexpr int WN = BN / 32;
    constexpr int WM = 8 / WN;
    constexpr int TM = 128 / WM;
    constexpr int MT = TM / 16;
    constexpr int CH = KTOT / 32;
    constexpr int ABUF = 128 * BKP;
    constexpr int BBUF = BN * BKP;

    extern __shared__ char sm[];
    bf16* sA = reinterpret_cast<bf16*>(sm);
    bf16* sB = reinterpret_cast<bf16*>(sm) + 4 * ABUF;
    __shared__ float s_bias[BN];
    __shared__ float s_w4[OUTMODE == 2 ? 64 : 1];
    __shared__ float s_red[OUTMODE == 2 ? 128 : 1][OUTMODE == 2 ? 2 : 1];

    const int tid = threadIdx.x;
    const int lane = tid & 31, wid = tid >> 5;
    const int g = lane >> 2, t = lane & 3;
    const int wn = wid % WN, wm = wid / WN;
    const int mrow = wm * TM, nrow = wn * 32;
    const int b = blockIdx.z;
    const int q0 = blockIdx.x * 128;
    const int gy = blockIdx.y;
    const size_t bR = (size_t)b * NROWS;
    const int arow = (lane & 7) + ((lane >> 3) & 1) * 8;
    const int acol = (lane >> 4) * 8;
    const int l15 = lane & 15;
    const int brow = l15 & 7;
    const int bcol = ((l15 >> 3) & 1) * 8;

    if (HASBIAS)
        for (int i = tid; i < BN; i += 256) s_bias[i] = bias[gy * BN + i];
    if (OUTMODE == 2 && tid < 64) s_w4[tid] = w4[tid];

    float acc[MT][4][4];
    #pragma unroll
    for (int mt = 0; mt < MT; mt++)
        #pragma unroll
        for (int nt = 0; nt < 4; nt++)
            #pragma unroll
            for (int i = 0; i < 4; i++) acc[mt][nt][i] = 0.f;

    auto load_chunk = [&](int s, int buf) {
        const int k0 = s * 32;
        #pragma unroll
        for (int i = 0; i < 4; i++) {
            int idx = tid + i * 256;
            int sel = idx >> 9, w = idx & 511, row = w >> 2, c = w & 3;
            const bf16* src = (sel ? Al : Ah) + (bR + q0 + row) * (size_t)KTOT + k0 + c * 8;
            cp16(smem_u32(sA + (buf * 2 + sel) * ABUF + row * BKP + c * 8), src);
        }
        #pragma unroll
        for (int i = 0; i < (BN * 8) / 256; i++) {
            int idx = tid + i * 256;
            int sel = (idx >= BN * 4) ? 1 : 0;
            int w = idx - sel * BN * 4, row = w >> 2, c = w & 3;
            const bf16* src = (sel ? Bl : Bh) + (size_t)(gy * BN + row) * KTOT + k0 + c * 8;
            cp16(smem_u32(sB + (buf * 2 + sel) * BBUF + row * BKP + c * 8), src);
        }
        CP_COMMIT();
    };

    load_chunk(0, 0);
    #pragma unroll 1
    for (int s = 0; s < CH; s++) {
        const int buf = s & 1;
        if (s + 1 < CH) { load_chunk(s + 1, buf ^ 1); cp_wait<1>(); }
        else cp_wait<0>();
        __syncthreads();
        const bf16* A0 = sA + (buf * 2 + 0) * ABUF;
        const bf16* A1 = sA + (buf * 2 + 1) * ABUF;
        const bf16* B0 = sB + (buf * 2 + 0) * BBUF;
        const bf16* B1 = sB + (buf * 2 + 1) * BBUF;
        #pragma unroll
        for (int ks = 0; ks < 2; ks++) {
            const int kb0 = ks * 16;
            uint32_t bh[4][2], bl[4][2];
            #pragma unroll
            for (int nt = 0; nt < 4; nt++) {
                LDSM_X2(bh[nt][0], bh[nt][1],
                        smem_u32(B0 + (nrow + nt * 8 + brow) * BKP + kb0 + bcol));
                LDSM_X2(bl[nt][0], bl[nt][1],
                        smem_u32(B1 + (nrow + nt * 8 + brow) * BKP + kb0 + bcol));
            }
            #pragma unroll
            for (int mt = 0; mt < MT; mt++) {
                uint32_t ah0, ah1, ah2, ah3, al0, al1, al2, al3;
                LDSM_X4(ah0, ah1, ah2, ah3,
                        smem_u32(A0 + (mrow + mt * 16 + arow) * BKP + kb0 + acol));
                LDSM_X4(al0, al1, al2, al3,
                        smem_u32(A1 + (mrow + mt * 16 + arow) * BKP + kb0 + acol));
                #pragma unroll
                for (int nt = 0; nt < 4; nt++) {
                    MMA_BF16(acc[mt][nt], ah0, ah1, ah2, ah3, bh[nt][0], bh[nt][1]);
                    MMA_BF16(acc[mt][nt], ah0, ah1, ah2, ah3, bl[nt][0], bl[nt][1]);
                    MMA_BF16(acc[mt][nt], al0, al1, al2, al3, bh[nt][0], bh[nt][1]);
                }
            }
        }
        __syncthreads();
    }

    if (OUTMODE == 2) {
        float pr[MT][2];
        #pragma unroll
        for (int mt = 0; mt < MT; mt++) { pr[mt][0] = 0.f; pr[mt][1] = 0.f; }
        #pragma unroll
        for (int mt = 0; mt < MT; mt++) {
            #pragma unroll
            for (int nt = 0; nt < 4; nt++) {
                int nl = nrow + nt * 8 + t * 2;
                float bi0 = s_bias[nl], bi1 = s_bias[nl + 1];
                float w40 = s_w4[nl], w41 = s_w4[nl + 1];
                pr[mt][0] += fmaxf(acc[mt][nt][0] + bi0, 0.f) * w40
                           + fmaxf(acc[mt][nt][1] + bi1, 0.f) * w41;
                pr[mt][1] += fmaxf(acc[mt][nt][2] + bi0, 0.f) * w40
                           + fmaxf(acc[mt][nt][3] + bi1, 0.f) * w41;
            }
        }
        #pragma unroll
        for (int mt = 0; mt < MT; mt++) {
            #pragma unroll
            for (int j = 0; j < 2; j++) {
                float p = pr[mt][j];
                p += __shfl_down_sync(0xFFFFFFFFu, p, 1, 4);
                p += __shfl_down_sync(0xFFFFFFFFu, p, 2, 4);
                if (t == 0) s_red[mrow + mt * 16 + g + j * 8][wn] = p;
            }
        }
        __syncthreads();
        if (tid < 128)
            ofp[bR + q0 + tid] = s_red[tid][0] + s_red[tid][1] + rb4[0];
        return;
    }

    #pragma unroll
    for (int mt = 0; mt < MT; mt++) {
        #pragma unroll
        for (int nt = 0; nt < 4; nt++) {
            int nl = nrow + nt * 8 + t * 2;
            int nn = gy * BN + nl;
            float bi0 = HASBIAS ? s_bias[nl] : 0.f;
            float bi1 = HASBIAS ? s_bias[nl + 1] : 0.f;
            size_t r0 = bR + q0 + mrow + mt * 16 + g;
            size_t r1 = r0 + 8;
            float v00 = acc[mt][nt][0] + bi0, v01 = acc[mt][nt][1] + bi1;
            float v10 = acc[mt][nt][2] + bi0, v11 = acc[mt][nt][3] + bi1;
            if (RELU) {
                v00 = fmaxf(v00, 0.f); v01 = fmaxf(v01, 0.f);
                v10 = fmaxf(v10, 0.f); v11 = fmaxf(v11, 0.f);
            }
            if (OUTMODE == 1) {
                unsigned lo0, lo1;
                unsigned hi0 = pack2b(v00, v01, lo0);
                unsigned hi1 = pack2b(v10, v11, lo1);
                *reinterpret_cast<unsigned*>(oh + r0 * NCHT + nn) = hi0;
                *reinterpret_cast<unsigned*>(ol + r0 * NCHT + nn) = lo0;
                *reinterpret_cast<unsigned*>(oh + r1 * NCHT + nn) = hi1;
                *reinterpret_cast<unsigned*>(ol + r1 * NCHT + nn) = lo1;
            } else {
                *reinterpret_cast<float2*>(ofp + r0 * NCHT + nn) = make_float2(v00, v01);
                *reinterpret_cast<float2*>(ofp + r1 * NCHT + nn) = make_float2(v10, v11);
            }
        }
    }
}

// ---------------- launch ----------------
extern "C" void kernel_launch(void* const* d_in, const int* in_sizes, int n_in,
                              void* d_out, int out_size) {
    (void)in_sizes; (void)n_in; (void)out_size;
    const float* orig = (const float*)d_in[0];
    const float* qpts = (const float*)d_in[1];
    const float* w1 = (const float*)d_in[2];
    const float* b1 = (const float*)d_in[3];
    const float* w2 = (const float*)d_in[4];
    const float* b2 = (const float*)d_in[5];
    const float* w3 = (const float*)d_in[6];
    const float* b3 = (const float*)d_in[7];
    const float* r1 = (const float*)d_in[8];
    const float* rb1 = (const float*)d_in[9];
    const float* r2 = (const float*)d_in[10];
    const float* rb2 = (const float*)d_in[11];
    const float* r3 = (const float*)d_in[12];
    const float* rb3 = (const float*)d_in[13];
    const float* r4 = (const float*)d_in[14];
    const float* rb4 = (const float*)d_in[15];
    float* out = (float*)d_out;

    float *pf1, *pf2, *pf3, *pG;
    cudaGetSymbolAddress((void**)&pf1, d_f1);
    cudaGetSymbolAddress((void**)&pf2, d_f2);
    cudaGetSymbolAddress((void**)&pf3, d_f3);
    cudaGetSymbolAddress((void**)&pG, d_G);
    bf16 *pfTh, *pfTl, *pW1h, *pW1l, *pW2h, *pW2l, *pW3h, *pW3l;
    bf16 *pH1h, *pH1l, *pH2h, *pH2l;
    cudaGetSymbolAddress((void**)&pfTh, d_fTh);
    cudaGetSymbolAddress((void**)&pfTl, d_fTl);
    cudaGetSymbolAddress((void**)&pW1h, d_w1h);
    cudaGetSymbolAddress((void**)&pW1l, d_w1l);
    cudaGetSymbolAddress((void**)&pW2h, d_w2h);
    cudaGetSymbolAddress((void**)&pW2l, d_w2l);
    cudaGetSymbolAddress((void**)&pW3h, d_w3h);
    cudaGetSymbolAddress((void**)&pW3l, d_w3l);
    cudaGetSymbolAddress((void**)&pH1h, d_h1h);
    cudaGetSymbolAddress((void**)&pH1l, d_h1l);
    cudaGetSymbolAddress((void**)&pH2h, d_h2h);
    cudaGetSymbolAddress((void**)&pH2l, d_h2l);

    const int SM128 = (4 * 128 * 40 + 4 * 128 * 40) * 2;  // 81920
    const int SM64  = (4 * 128 * 40 + 4 * 64 * 40) * 2;   // 61440
    const int SMKNN = N_ * 16 + 64 * 4 * 3 * 8;           // 71680
    cudaFuncSetAttribute(wmma_layer<128, 256, 448, N_, false, false, 0>,
                         cudaFuncAttributeMaxDynamicSharedMemorySize, SM128);
    cudaFuncSetAttribute(wmma_layer<128, 128, 256, Q_, true, true, 1>,
                         cudaFuncAttributeMaxDynamicSharedMemorySize, SM128);
    cudaFuncSetAttribute(wmma_layer<64, 64, 128, Q_, true, true, 2>,
                         cudaFuncAttributeMaxDynamicSharedMemorySize, SM64);
    cudaFuncSetAttribute(knn_idx_kernel,
                         cudaFuncAttributeMaxDynamicSharedMemorySize, SMKNN);

    // Fork: run KNN concurrently with the feature/G chain on a second stream.
    // Host-side stream/event objects only (no device allocation); the
    // event-record / wait-event pattern is the documented capture fork-join.
    static cudaStream_t s2 = nullptr;
    static cudaEvent_t evF = nullptr, evJ = nullptr;
    if (s2 == nullptr) {
        cudaStreamCreateWithFlags(&s2, cudaStreamNonBlocking);
        cudaEventCreateWithFlags(&evF, cudaEventDisableTiming);
        cudaEventCreateWithFlags(&evJ, cudaEventDisableTiming);
    }

    cudaEventRecord(evF, 0);
    cudaStreamWaitEvent(s2, evF, 0);
    knn_idx_kernel<<<dim3(Q_ / 64, B_), 256, SMKNN, s2>>>(orig, qpts);
    cudaEventRecord(evJ, s2);

    feat1_kernel<<<dim3(N_ / 256, B_), 256>>>(orig, w1, b1);
    feat_layer_kernel<64><<<dim3(N_ / 256, 16, B_), 256>>>(pf1, w2, b2, pf2, 128);
    feat_layer_kernel<128><<<dim3(N_ / 256, 32, B_), 256>>>(pf2, w3, b3, pf3, 256);
    gmax_kernel<<<dim3(256, B_), 256>>>();
    gconst_kernel<<<B_, 256>>>(r1, rb1);
    build_fT_kernel<<<dim3(N_ / 32, 14, B_), dim3(32, 8)>>>();
    wprep_kernel<<<256, 128>>>(r1, 707, 448, 3, pW1h, pW1l);
    wprep_kernel<<<128, 128>>>(r2, 256, 256, 0, pW2h, pW2l);
    wprep_kernel<<<64, 128>>>(r3, 128, 128, 0, pW3h, pW3l);

    wmma_layer<128, 256, 448, N_, false, false, 0><<<dim3(N_ / 128, 2, B_), 256, SM128>>>(
        pfTh, pfTl, pW1h, pW1l, nullptr, nullptr, nullptr, nullptr, nullptr, pG);

    cudaStreamWaitEvent(0, evJ, 0);   // join: gather needs d_knn + d_G + d_wqgc
    gather_h1_kernel<<<dim3(Q_ / 256, B_), 256>>>(qpts);
    wmma_layer<128, 128, 256, Q_, true, true, 1><<<dim3(Q_ / 128, 1, B_), 256, SM128>>>(
        pH1h, pH1l, pW2h, pW2l, rb2, nullptr, nullptr, pH2h, pH2l, nullptr);
    wmma_layer<64, 64, 128, Q_, true, true, 2><<<dim3(Q_ / 128, 1, B_), 256, SM64>>>(
        pH2h, pH2l, pW3h, pW3l, rb3, r4, rb4, nullptr, nullptr, out);
}

// round 14
// speedup vs baseline: 1.2633x; 1.0841x over previous
#include <cuda_runtime.h>
#include <cuda_bf16.h>
#include <cstdint>
#include <cstddef>

#define N_ 4096
#define Q_ 16384
#define B_ 2
typedef __nv_bfloat16 bf16;

// ---------------- static scratch ----------------
__device__ unsigned d_gu[B_ * 256];
__device__ float4 d_wqgc[B_ * 256];
__device__ float d_G[(size_t)B_ * N_ * 256];
__device__ float4 d_knn[(size_t)B_ * Q_ * 2];
__device__ bf16 d_fTh[(size_t)B_ * N_ * 448];
__device__ bf16 d_fTl[(size_t)B_ * N_ * 448];
__device__ bf16 d_h1h[(size_t)B_ * Q_ * 256];
__device__ bf16 d_h1l[(size_t)B_ * Q_ * 256];
__device__ bf16 d_h2h[(size_t)B_ * Q_ * 128];
__device__ bf16 d_h2l[(size_t)B_ * Q_ * 128];
__device__ bf16 d_w1h[256 * 448];
__device__ bf16 d_w1l[256 * 448];
__device__ bf16 d_w2h[128 * 64];
__device__ bf16 d_w2l[128 * 64];
__device__ bf16 d_w3h[256 * 128];
__device__ bf16 d_w3l[256 * 128];
__device__ bf16 d_r2h[128 * 256];
__device__ bf16 d_r2l[128 * 256];
__device__ bf16 d_r3h[64 * 128];
__device__ bf16 d_r3l[64 * 128];

// ---------------- helpers ----------------
__device__ __forceinline__ uint32_t smem_u32(const void* p) {
    uint32_t a;
    asm("{ .reg .u64 t; cvta.to.shared.u64 t, %1; cvt.u32.u64 %0, t; }" : "=r"(a) : "l"(p));
    return a;
}
__device__ __forceinline__ void cp16(uint32_t s, const void* g) {
    asm volatile("cp.async.cg.shared.global [%0], [%1], 16;" :: "r"(s), "l"(g));
}
#define CP_COMMIT() asm volatile("cp.async.commit_group;" ::: "memory")
template<int NN> __device__ __forceinline__ void cp_wait() {
    asm volatile("cp.async.wait_group %0;" :: "n"(NN) : "memory");
}
#define MMA_BF16(d, a0, a1, a2, a3, b0, b1) \
    asm volatile("mma.sync.aligned.m16n8k16.row.col.f32.bf16.bf16.f32 " \
        "{%0,%1,%2,%3}, {%4,%5,%6,%7}, {%8,%9}, {%0,%1,%2,%3};" \
        : "+f"((d)[0]), "+f"((d)[1]), "+f"((d)[2]), "+f"((d)[3]) \
        : "r"(a0), "r"(a1), "r"(a2), "r"(a3), "r"(b0), "r"(b1))
#define LDSM_X4(r0, r1, r2, r3, addr) \
    asm volatile("ldmatrix.sync.aligned.m8n8.x4.shared.b16 {%0,%1,%2,%3}, [%4];" \
        : "=r"(r0), "=r"(r1), "=r"(r2), "=r"(r3) : "r"(addr))
#define LDSM_X2(r0, r1, addr) \
    asm volatile("ldmatrix.sync.aligned.m8n8.x2.shared.b16 {%0,%1}, [%2];" \
        : "=r"(r0), "=r"(r1) : "r"(addr))

__device__ __forceinline__ unsigned pack2b(float v0, float v1, unsigned& lo) {
    bf16 h0 = __float2bfloat16(v0), h1 = __float2bfloat16(v1);
    bf16 l0 = __float2bfloat16(v0 - __bfloat162float(h0));
    bf16 l1 = __float2bfloat16(v1 - __bfloat162float(h1));
    lo = (unsigned)__bfloat16_as_ushort(l0) | ((unsigned)__bfloat16_as_ushort(l1) << 16);
    return (unsigned)__bfloat16_as_ushort(h0) | ((unsigned)__bfloat16_as_ushort(h1) << 16);
}

// ---------------- feature layer 1: 3 -> 64, writes fT cols [0,64) ----------------
__global__ void feat1_kernel(const float* __restrict__ orig,
                             const float* __restrict__ w1, const float* __restrict__ b1) {
    __shared__ float ws[192], bs[64];
    int tid = threadIdx.x;
    if (tid < 192) ws[tid] = w1[tid];
    if (tid < 64) bs[tid] = b1[tid];
    __syncthreads();
    int b = blockIdx.y, n = blockIdx.x * 256 + tid;
    const float* ob = orig + (size_t)b * 3 * N_;
    float x = ob[n], y = ob[N_ + n], z = ob[2 * N_ + n];
    size_t ro = ((size_t)b * N_ + n) * 448;
    #pragma unroll
    for (int c = 0; c < 64; c += 2) {
        float v0 = fmaxf(fmaf(ws[c * 3], x, fmaf(ws[c * 3 + 1], y,
                        fmaf(ws[c * 3 + 2], z, bs[c]))), 0.f);
        float v1 = fmaxf(fmaf(ws[c * 3 + 3], x, fmaf(ws[c * 3 + 4], y,
                        fmaf(ws[c * 3 + 5], z, bs[c + 1]))), 0.f);
        unsigned lo;
        unsigned hi = pack2b(v0, v1, lo);
        *reinterpret_cast<unsigned*>(d_fTh + ro + c) = hi;
        *reinterpret_cast<unsigned*>(d_fTl + ro + c) = lo;
    }
}

__global__ void gzero_kernel() { d_gu[blockIdx.x * 256 + threadIdx.x] = 0u; }

// global max over n of fT cols [192,448)  (values are post-relu >= 0)
__global__ void gmax_kernel() {
    int b = blockIdx.y, c = threadIdx.x;
    int n0 = blockIdx.x * 256;
    float m = 0.f;
    for (int i = 0; i < 256; i++) {
        size_t o = ((size_t)b * N_ + n0 + i) * 448 + 192 + c;
        m = fmaxf(m, __bfloat162float(d_fTh[o]) + __bfloat162float(d_fTl[o]));
    }
    atomicMax(&d_gu[b * 256 + c], __float_as_uint(m));
}

__global__ void gconst_kernel(const float* __restrict__ r1, const float* __restrict__ rb1) {
    __shared__ float gs[256];
    int b = blockIdx.x, m = threadIdx.x;
    gs[m] = __uint_as_float(d_gu[b * 256 + m]);
    __syncthreads();
    float a = rb1[m];
    const float* wr = r1 + (size_t)m * 707 + 451;
    #pragma unroll 4
    for (int c = 0; c < 256; c++) a = fmaf(wr[c], gs[c], a);
    d_wqgc[b * 256 + m] = make_float4(r1[(size_t)m * 707 + 0], r1[(size_t)m * 707 + 1],
                                      r1[(size_t)m * 707 + 2], a);
}

__global__ void wprep_kernel(const float* __restrict__ src, int srcld, int Kdst, int coff,
                             bf16* __restrict__ dh, bf16* __restrict__ dl) {
    int m = blockIdx.x;
    for (int c = threadIdx.x; c < Kdst; c += blockDim.x) {
        float v = src[(size_t)m * srcld + coff + c];
        bf16 h = __float2bfloat16(v);
        dh[(size_t)m * Kdst + c] = h;
        dl[(size_t)m * Kdst + c] = __float2bfloat16(v - __bfloat162float(h));
    }
}

// ---------------- KNN(K=3), 4-way slice split (exact) ----------------
__global__ void knn_idx_kernel(const float* __restrict__ orig, const float* __restrict__ qpts) {
    extern __shared__ char smraw[];
    float4* op = reinterpret_cast<float4*>(smraw);                 // [4096]
    float* cd = reinterpret_cast<float*>(smraw + 65536);           // [64][4][3]
    int* ci = reinterpret_cast<int*>(smraw + 65536 + 3072);        // [64][4][3]
    int b = blockIdx.y;
    const float* ob = orig + (size_t)b * 3 * N_;
    for (int i = threadIdx.x; i < N_; i += 256) {
        float x = ob[i], y = ob[N_ + i], z = ob[2 * N_ + i];
        op[i] = make_float4(x, y, z, fmaf(x, x, fmaf(y, y, z * z)));
    }
    __syncthreads();

    const int ql = threadIdx.x & 63, sl = threadIdx.x >> 6;
    const int q = blockIdx.x * 64 + ql;
    const float* qb = qpts + (size_t)b * 3 * Q_;
    const float qx = qb[q], qy = qb[Q_ + q], qz = qb[2 * Q_ + q];
    const float qa = -2.f * qx, qc = -2.f * qy, qd = -2.f * qz;

    float b0 = 1e30f, b1 = 1e30f, b2 = 1e30f;
    int i0 = -1, i1 = -1, i2 = -1;
    const int jbeg = sl * (N_ / 4), jend = jbeg + N_ / 4;
    #pragma unroll 4
    for (int j = jbeg; j < jend; j++) {
        float4 P = op[j];
        float d = fmaf(P.x, qa, fmaf(P.y, qc, fmaf(P.z, qd, P.w)));
        if (d < b2) {
            if (d < b1) {
                b2 = b1; i2 = i1;
                if (d < b0) { b1 = b0; i1 = i0; b0 = d; i0 = j; }
                else        { b1 = d; i1 = j; }
            } else { b2 = d; i2 = j; }
        }
    }
    {
        int base = (ql * 4 + sl) * 3;
        cd[base + 0] = b0; cd[base + 1] = b1; cd[base + 2] = b2;
        ci[base + 0] = i0; ci[base + 1] = i1; ci[base + 2] = i2;
    }
    __syncthreads();

    if (threadIdx.x < 64) {
        const int qq = blockIdx.x * 64 + threadIdx.x;
        float m0 = 1e30f, m1 = 1e30f, m2 = 1e30f;
        int j0 = 0, j1 = 0, j2 = 0;
        int base = threadIdx.x * 12;
        #pragma unroll
        for (int c = 0; c < 12; c++) {
            float d = cd[base + c];
            int j = ci[base + c];
            if (d < m2) {
                if (d < m1) {
                    m2 = m1; j2 = j1;
                    if (d < m0) { m1 = m0; j1 = j0; m0 = d; j0 = j; }
                    else        { m1 = d; j1 = j; }
                } else { m2 = d; j2 = j; }
            }
        }
        const float tqx = qb[qq], tqy = qb[Q_ + qq], tqz = qb[2 * Q_ + qq];
        float4 P0 = op[j0], P1 = op[j1], P2 = op[j2];
        float dx, dy, dz;
        dx = tqx - P0.x; dy = tqy - P0.y; dz = tqz - P0.z;
        float e0 = sqrtf(fmaf(dx, dx, fmaf(dy, dy, dz * dz)));
        dx = tqx - P1.x; dy = tqy - P1.y; dz = tqz - P1.z;
        float e1 = sqrtf(fmaf(dx, dx, fmaf(dy, dy, dz * dz)));
        dx = tqx - P2.x; dy = tqy - P2.y; dz = tqz - P2.z;
        float e2 = sqrtf(fmaf(dx, dx, fmaf(dy, dy, dz * dz)));
        float r0 = 1.f / (e0 + 1e-8f);
        float r1 = 1.f / (e1 + 1e-8f);
        float r2 = 1.f / (e2 + 1e-8f);
        float s = r0 + r1 + r2;
        size_t o = ((size_t)b * Q_ + qq) * 2;
        d_knn[o] = make_float4(__int_as_float(j0), __int_as_float(j1), __int_as_float(j2), r0 / s);
        d_knn[o + 1] = make_float4(r1 / s, r2 / s, 0.f, 0.f);
    }
}

// ---------------- gather G rows + fused layer-1 ----------------
__global__ void gather_h1_kernel(const float* __restrict__ qpts) {
    __shared__ float4 swq[256];
    int b = blockIdx.y;
    for (int i = threadIdx.x; i < 256; i += blockDim.x) swq[i] = d_wqgc[b * 256 + i];
    __syncthreads();
    int q = blockIdx.x * blockDim.x + threadIdx.x;
    const float* qb = qpts + (size_t)b * 3 * Q_;
    float qx = qb[q], qy = qb[Q_ + q], qz = qb[2 * Q_ + q];
    size_t o = ((size_t)b * Q_ + q) * 2;
    float4 rec0 = d_knn[o], rec1 = d_knn[o + 1];
    int i0 = __float_as_int(rec0.x), i1 = __float_as_int(rec0.y), i2 = __float_as_int(rec0.z);
    float w0 = rec0.w, w1 = rec1.x, w2 = rec1.y;

    const float4* G0 = reinterpret_cast<const float4*>(d_G + ((size_t)b * N_ + i0) * 256);
    const float4* G1 = reinterpret_cast<const float4*>(d_G + ((size_t)b * N_ + i1) * 256);
    const float4* G2 = reinterpret_cast<const float4*>(d_G + ((size_t)b * N_ + i2) * 256);
    size_t ro = ((size_t)b * Q_ + q) * 256;
    uint2* rh = reinterpret_cast<uint2*>(d_h1h + ro);
    uint2* rl = reinterpret_cast<uint2*>(d_h1l + ro);
    #pragma unroll 4
    for (int c4 = 0; c4 < 64; c4++) {
        float4 g0 = G0[c4], g1 = G1[c4], g2 = G2[c4];
        float4 m0 = swq[c4 * 4 + 0], m1 = swq[c4 * 4 + 1];
        float4 m2 = swq[c4 * 4 + 2], m3 = swq[c4 * 4 + 3];
        float v0 = fmaf(w0, g0.x, fmaf(w1, g1.x, fmaf(w2, g2.x,
                   fmaf(qx, m0.x, fmaf(qy, m0.y, fmaf(qz, m0.z, m0.w))))));
        float v1 = fmaf(w0, g0.y, fmaf(w1, g1.y, fmaf(w2, g2.y,
                   fmaf(qx, m1.x, fmaf(qy, m1.y, fmaf(qz, m1.z, m1.w))))));
        float v2 = fmaf(w0, g0.z, fmaf(w1, g1.z, fmaf(w2, g2.z,
                   fmaf(qx, m2.x, fmaf(qy, m2.y, fmaf(qz, m2.z, m2.w))))));
        float v3 = fmaf(w0, g0.w, fmaf(w1, g1.w, fmaf(w2, g2.w,
                   fmaf(qx, m3.x, fmaf(qy, m3.y, fmaf(qz, m3.z, m3.w))))));
        v0 = fmaxf(v0, 0.f); v1 = fmaxf(v1, 0.f);
        v2 = fmaxf(v2, 0.f); v3 = fmaxf(v3, 0.f);
        uint2 hh, ll;
        hh.x = pack2b(v0, v1, ll.x);
        hh.y = pack2b(v2, v3, ll.y);
        rh[c4] = hh; rl[c4] = ll;
    }
}

// ---------------- split-bf16 GEMM via mma.sync + ldmatrix ----------------
// OUTMODE: 0 = f32 rows, 1 = bf16 hi/lo rows, 2 = fused final 64->1 dot
template<int BN, int OST, int K, int LDA, int NROWS, bool HASBIAS, bool RELU, int OUTMODE>
__global__ void __launch_bounds__(256)
wmma_layer(const bf16* __restrict__ Ah, const bf16* __restrict__ Al,
           const bf16* __restrict__ Bh, const bf16* __restrict__ Bl,
           const float* __restrict__ bias,
           const float* __restrict__ w4, const float* __restrict__ rb4,
           bf16* __restrict__ oh, bf16* __restrict__ ol, float* __restrict__ ofp) {
    constexpr int BKP = 40;
    constexpr int WN = BN / 32;
    constexpr int WM = 8 / WN;
    constexpr int TM = 128 / WM;
    constexpr int MT = TM / 16;
    constexpr int CH = K / 32;
    constexpr int ABUF = 128 * BKP;
    constexpr int BBUF = BN * BKP;

    extern __shared__ char sm[];
    bf16* sA = reinterpret_cast<bf16*>(sm);
    bf16* sB = reinterpret_cast<bf16*>(sm) + 4 * ABUF;
    __shared__ float s_bias[BN];
    __shared__ float s_w4[OUTMODE == 2 ? 64 : 1];
    __shared__ float s_red[OUTMODE == 2 ? 128 : 1][OUTMODE == 2 ? 2 : 1];

    const int tid = threadIdx.x;
    const int lane = tid & 31, wid = tid >> 5;
    const int g = lane >> 2, t = lane & 3;
    const int wn = wid % WN, wm = wid / WN;
    const int mrow = wm * TM, nrow = wn * 32;
    const int b = blockIdx.z;
    const int q0 = blockIdx.x * 128;
    const int gy = blockIdx.y;
    const size_t bR = (size_t)b * NROWS;
    const int arow = (lane & 7) + ((lane >> 3) & 1) * 8;
    const int acol = (lane >> 4) * 8;
    const int l15 = lane & 15;
    const int brow = l15 & 7;
    const int bcol = ((l15 >> 3) & 1) * 8;

    if (HASBIAS)
        for (int i = tid; i < BN; i += 256) s_bias[i] = bias[gy * BN + i];
    if (OUTMODE == 2 && tid < 64) s_w4[tid] = w4[tid];

    float acc[MT][4][4];
    #pragma unroll
    for (int mt = 0; mt < MT; mt++)
        #pragma unroll
        for (int nt = 0; nt < 4; nt++)
            #pragma unroll
            for (int i = 0; i < 4; i++) acc[mt][nt][i] = 0.f;

    auto load_chunk = [&](int s, int buf) {
        const int k0 = s * 32;
        #pragma unroll
        for (int i = 0; i < 4; i++) {
            int idx = tid + i * 256;
            int sel = idx >> 9, w = idx & 511, row = w >> 2, c = w & 3;
            const bf16* src = (sel ? Al : Ah) + (bR + q0 + row) * (size_t)LDA + k0 + c * 8;
            cp16(smem_u32(sA + (buf * 2 + sel) * ABUF + row * BKP + c * 8), src);
        }
        #pragma unroll
        for (int i = 0; i < (BN * 8) / 256; i++) {
            int idx = tid + i * 256;
            int sel = (idx >= BN * 4) ? 1 : 0;
            int w = idx - sel * BN * 4, row = w >> 2, c = w & 3;
            const bf16* src = (sel ? Bl : Bh) + (size_t)(gy * BN + row) * K + k0 + c * 8;
            cp16(smem_u32(sB + (buf * 2 + sel) * BBUF + row * BKP + c * 8), src);
        }
        CP_COMMIT();
    };

    load_chunk(0, 0);
    #pragma unroll 1
    for (int s = 0; s < CH; s++) {
        const int buf = s & 1;
        if (s + 1 < CH) { load_chunk(s + 1, buf ^ 1); cp_wait<1>(); }
        else cp_wait<0>();
        __syncthreads();
        const bf16* A0 = sA + (buf * 2 + 0) * ABUF;
        const bf16* A1 = sA + (buf * 2 + 1) * ABUF;
        const bf16* B0 = sB + (buf * 2 + 0) * BBUF;
        const bf16* B1 = sB + (buf * 2 + 1) * BBUF;
        #pragma unroll
        for (int ks = 0; ks < 2; ks++) {
            const int kb0 = ks * 16;
            uint32_t bh[4][2], bl[4][2];
            #pragma unroll
            for (int nt = 0; nt < 4; nt++) {
                LDSM_X2(bh[nt][0], bh[nt][1],
                        smem_u32(B0 + (nrow + nt * 8 + brow) * BKP + kb0 + bcol));
                LDSM_X2(bl[nt][0], bl[nt][1],
                        smem_u32(B1 + (nrow + nt * 8 + brow) * BKP + kb0 + bcol));
            }
            #pragma unroll
            for (int mt = 0; mt < MT; mt++) {
                uint32_t ah0, ah1, ah2, ah3, al0, al1, al2, al3;
                LDSM_X4(ah0, ah1, ah2, ah3,
                        smem_u32(A0 + (mrow + mt * 16 + arow) * BKP + kb0 + acol));
                LDSM_X4(al0, al1, al2, al3,
                        smem_u32(A1 + (mrow + mt * 16 + arow) * BKP + kb0 + acol));
                #pragma unroll
                for (int nt = 0; nt < 4; nt++) {
                    MMA_BF16(acc[mt][nt], ah0, ah1, ah2, ah3, bh[nt][0], bh[nt][1]);
                    MMA_BF16(acc[mt][nt], ah0, ah1, ah2, ah3, bl[nt][0], bl[nt][1]);
                    MMA_BF16(acc[mt][nt], al0, al1, al2, al3, bh[nt][0], bh[nt][1]);
                }
            }
        }
        __syncthreads();
    }

    if (OUTMODE == 2) {
        float pr[MT][2];
        #pragma unroll
        for (int mt = 0; mt < MT; mt++) { pr[mt][0] = 0.f; pr[mt][1] = 0.f; }
        #pragma unroll
        for (int mt = 0; mt < MT; mt++) {
            #pragma unroll
            for (int nt = 0; nt < 4; nt++) {
                int nl = nrow + nt * 8 + t * 2;
                float bi0 = s_bias[nl], bi1 = s_bias[nl + 1];
                float w40 = s_w4[nl], w41 = s_w4[nl + 1];
                pr[mt][0] += fmaxf(acc[mt][nt][0] + bi0, 0.f) * w40
                           + fmaxf(acc[mt][nt][1] + bi1, 0.f) * w41;
                pr[mt][1] += fmaxf(acc[mt][nt][2] + bi0, 0.f) * w40
                           + fmaxf(acc[mt][nt][3] + bi1, 0.f) * w41;
            }
        }
        #pragma unroll
        for (int mt = 0; mt < MT; mt++) {
            #pragma unroll
            for (int j = 0; j < 2; j++) {
                float p = pr[mt][j];
                p += __shfl_down_sync(0xFFFFFFFFu, p, 1, 4);
                p += __shfl_down_sync(0xFFFFFFFFu, p, 2, 4);
                if (t == 0) s_red[mrow + mt * 16 + g + j * 8][wn] = p;
            }
        }
        __syncthreads();
        if (tid < 128)
            ofp[bR + q0 + tid] = s_red[tid][0] + s_red[tid][1] + rb4[0];
        return;
    }

    #pragma unroll
    for (int mt = 0; mt < MT; mt++) {
        #pragma unroll
        for (int nt = 0; nt < 4; nt++) {
            int nl = nrow + nt * 8 + t * 2;
            int nn = gy * BN + nl;
            float bi0 = HASBIAS ? s_bias[nl] : 0.f;
            float bi1 = HASBIAS ? s_bias[nl + 1] : 0.f;
            size_t r0 = bR + q0 + mrow + mt * 16 + g;
            size_t r1 = r0 + 8;
            float v00 = acc[mt][nt][0] + bi0, v01 = acc[mt][nt][1] + bi1;
            float v10 = acc[mt][nt][2] + bi0, v11 = acc[mt][nt][3] + bi1;
            if (RELU) {
                v00 = fmaxf(v00, 0.f); v01 = fmaxf(v01, 0.f);
                v10 = fmaxf(v10, 0.f); v11 = fmaxf(v11, 0.f);
            }
            if (OUTMODE == 1) {
                unsigned lo0, lo1;
                unsigned hi0 = pack2b(v00, v01, lo0);
                unsigned hi1 = pack2b(v10, v11, lo1);
                *reinterpret_cast<unsigned*>(oh + r0 * OST + nn) = hi0;
                *reinterpret_cast<unsigned*>(ol + r0 * OST + nn) = lo0;
                *reinterpret_cast<unsigned*>(oh + r1 * OST + nn) = hi1;
                *reinterpret_cast<unsigned*>(ol + r1 * OST + nn) = lo1;
            } else {
                *reinterpret_cast<float2*>(ofp + r0 * OST + nn) = make_float2(v00, v01);
                *reinterpret_cast<float2*>(ofp + r1 * OST + nn) = make_float2(v10, v11);
            }
        }
    }
}

// ---------------- launch ----------------
extern "C" void kernel_launch(void* const* d_in, const int* in_sizes, int n_in,
                              void* d_out, int out_size) {
    (void)in_sizes; (void)n_in; (void)out_size;
    const float* orig = (const float*)d_in[0];
    const float* qpts = (const float*)d_in[1];
    const float* w1 = (const float*)d_in[2];
    const float* b1 = (const float*)d_in[3];
    const float* w2 = (const float*)d_in[4];
    const float* b2 = (const float*)d_in[5];
    const float* w3 = (const float*)d_in[6];
    const float* b3 = (const float*)d_in[7];
    const float* r1 = (const float*)d_in[8];
    const float* rb1 = (const float*)d_in[9];
    const float* r2 = (const float*)d_in[10];
    const float* rb2 = (const float*)d_in[11];
    const float* r3 = (const float*)d_in[12];
    const float* rb3 = (const float*)d_in[13];
    const float* r4 = (const float*)d_in[14];
    const float* rb4 = (const float*)d_in[15];
    float* out = (float*)d_out;

    float* pG;
    cudaGetSymbolAddress((void**)&pG, d_G);
    bf16 *pfTh, *pfTl, *pW1h, *pW1l, *pW2h, *pW2l, *pW3h, *pW3l;
    bf16 *pR2h, *pR2l, *pR3h, *pR3l, *pH1h, *pH1l, *pH2h, *pH2l;
    cudaGetSymbolAddress((void**)&pfTh, d_fTh);
    cudaGetSymbolAddress((void**)&pfTl, d_fTl);
    cudaGetSymbolAddress((void**)&pW1h, d_w1h);
    cudaGetSymbolAddress((void**)&pW1l, d_w1l);
    cudaGetSymbolAddress((void**)&pW2h, d_w2h);
    cudaGetSymbolAddress((void**)&pW2l, d_w2l);
    cudaGetSymbolAddress((void**)&pW3h, d_w3h);
    cudaGetSymbolAddress((void**)&pW3l, d_w3l);
    cudaGetSymbolAddress((void**)&pR2h, d_r2h);
    cudaGetSymbolAddress((void**)&pR2l, d_r2l);
    cudaGetSymbolAddress((void**)&pR3h, d_r3h);
    cudaGetSymbolAddress((void**)&pR3l, d_r3l);
    cudaGetSymbolAddress((void**)&pH1h, d_h1h);
    cudaGetSymbolAddress((void**)&pH1l, d_h1l);
    cudaGetSymbolAddress((void**)&pH2h, d_h2h);
    cudaGetSymbolAddress((void**)&pH2l, d_h2l);

    const int SM128 = (4 * 128 * 40 + 4 * 128 * 40) * 2;  // 81920
    const int SM64  = (4 * 128 * 40 + 4 * 64 * 40) * 2;   // 61440
    const int SMKNN = N_ * 16 + 64 * 4 * 3 * 8;           // 71680
    cudaFuncSetAttribute(wmma_layer<128, 448, 64, 448, N_, true, true, 1>,
                         cudaFuncAttributeMaxDynamicSharedMemorySize, SM128);
    cudaFuncSetAttribute(wmma_layer<128, 448, 128, 448, N_, true, true, 1>,
                         cudaFuncAttributeMaxDynamicSharedMemorySize, SM128);
    cudaFuncSetAttribute(wmma_layer<128, 256, 448, 448, N_, false, false, 0>,
                         cudaFuncAttributeMaxDynamicSharedMemorySize, SM128);
    cudaFuncSetAttribute(wmma_layer<128, 128, 256, 256, Q_, true, true, 1>,
                         cudaFuncAttributeMaxDynamicSharedMemorySize, SM128);
    cudaFuncSetAttribute(wmma_layer<64, 1, 128, 128, Q_, true, true, 2>,
                         cudaFuncAttributeMaxDynamicSharedMemorySize, SM64);
    cudaFuncSetAttribute(knn_idx_kernel,
                         cudaFuncAttributeMaxDynamicSharedMemorySize, SMKNN);

    // Fork: KNN on a second stream, concurrent with the feature/G chain.
    static cudaStream_t s2 = nullptr;
    static cudaEvent_t evF = nullptr, evJ = nullptr;
    if (s2 == nullptr) {
        cudaStreamCreateWithFlags(&s2, cudaStreamNonBlocking);
        cudaEventCreateWithFlags(&evF, cudaEventDisableTiming);
        cudaEventCreateWithFlags(&evJ, cudaEventDisableTiming);
    }
    cudaEventRecord(evF, 0);
    cudaStreamWaitEvent(s2, evF, 0);
    knn_idx_kernel<<<dim3(Q_ / 64, B_), 256, SMKNN, s2>>>(orig, qpts);
    cudaEventRecord(evJ, s2);

    // feature chain (tensor-core): fT cols [0,64) <- feat1; [64,192) <- feat2; [192,448) <- feat3
    feat1_kernel<<<dim3(N_ / 256, B_), 256>>>(orig, w1, b1);
    wprep_kernel<<<128, 64>>>(w2, 64, 64, 0, pW2h, pW2l);
    wprep_kernel<<<256, 128>>>(w3, 128, 128, 0, pW3h, pW3l);
    wprep_kernel<<<256, 128>>>(r1, 707, 448, 3, pW1h, pW1l);
    wprep_kernel<<<128, 128>>>(r2, 256, 256, 0, pR2h, pR2l);
    wprep_kernel<<<64, 128>>>(r3, 128, 128, 0, pR3h, pR3l);
    wmma_layer<128, 448, 64, 448, N_, true, true, 1><<<dim3(N_ / 128, 1, B_), 256, SM128>>>(
        pfTh, pfTl, pW2h, pW2l, b2, nullptr, nullptr, pfTh + 64, pfTl + 64, nullptr);
    wmma_layer<128, 448, 128, 448, N_, true, true, 1><<<dim3(N_ / 128, 2, B_), 256, SM128>>>(
        pfTh + 64, pfTl + 64, pW3h, pW3l, b3, nullptr, nullptr, pfTh + 192, pfTl + 192, nullptr);
    gzero_kernel<<<2, 256>>>();
    gmax_kernel<<<dim3(16, B_), 256>>>();
    gconst_kernel<<<B_, 256>>>(r1, rb1);
    wmma_layer<128, 256, 448, 448, N_, false, false, 0><<<dim3(N_ / 128, 2, B_), 256, SM128>>>(
        pfTh, pfTl, pW1h, pW1l, nullptr, nullptr, nullptr, nullptr, nullptr, pG);

    cudaStreamWaitEvent(0, evJ, 0);   // join: gather needs d_knn + d_G + d_wqgc
    gather_h1_kernel<<<dim3(Q_ / 256, B_), 256>>>(qpts);
    wmma_layer<128, 128, 256, 256, Q_, true, true, 1><<<dim3(Q_ / 128, 1, B_), 256, SM128>>>(
        pH1h, pH1l, pR2h, pR2l, rb2, nullptr, nullptr, pH2h, pH2l, nullptr);
    wmma_layer<64, 1, 128, 128, Q_, true, true, 2><<<dim3(Q_ / 128, 1, B_), 256, SM64>>>(
        pH2h, pH2l, pR3h, pR3l, rb3, r4, rb4, nullptr, nullptr, out);
}